// round 3
// baseline (speedup 1.0000x reference)
#include <cuda_runtime.h>
#include <cuda_bf16.h>
#include <math.h>
#include <stdint.h>

// ---------------------------------------------------------------------------
// Problem constants
// ---------------------------------------------------------------------------
#define kN   6000
#define kR   1000
#define MAXN 0.996f
#define DD   (128*128)

// ---------------------------------------------------------------------------
// Static scratch pools (element offsets)
// ---------------------------------------------------------------------------
#define OF_RELAGG  0            // 2 x 768000
#define OF_HC      1536000      // 2 x 1536000  ([br][n][256])
#define OF_T3      4608000      // 1536000
#define OF_ES      7680000      // 24000
#define OF_ED      7704000      // 24000
#define OF_SEQ     7728000      // 4608000  ([br*6000+n][3][128])
#define OF_QB      12336000     // 9216000
#define OF_KB      21552000     // 9216000
#define OF_VB      30768000     // 9216000
#define OF_OC      39984000     // 9216000
#define OF_FCO     49200000     // 4608000
#define OF_T1      53808000     // 1536000
#define OF_T2      55344000     // 1536000
#define OF_BB      58416000     // 2 x 132
#define OF_VALS    58420000     // 1536000
__device__ float g_fpool[60000000];

#define IO_COLS 0               // 1536000
#define IO_CNT  1536000         // 12000
__device__ int g_ipool[1549000];

// ---------------------------------------------------------------------------
// Block reductions (blockDim.x == 128)
// ---------------------------------------------------------------------------
__device__ __forceinline__ float brsum128(float v) {
    __shared__ float sh[4];
    #pragma unroll
    for (int o = 16; o > 0; o >>= 1) v += __shfl_down_sync(0xffffffffu, v, o);
    __syncthreads();
    if ((threadIdx.x & 31) == 0) sh[threadIdx.x >> 5] = v;
    __syncthreads();
    return sh[0] + sh[1] + sh[2] + sh[3];
}

__device__ __forceinline__ float brmax128(float v) {
    __shared__ float shm[4];
    #pragma unroll
    for (int o = 16; o > 0; o >>= 1) v = fmaxf(v, __shfl_down_sync(0xffffffffu, v, o));
    __syncthreads();
    if ((threadIdx.x & 31) == 0) shm[threadIdx.x >> 5] = v;
    __syncthreads();
    return fmaxf(fmaxf(shm[0], shm[1]), fmaxf(shm[2], shm[3]));
}

// ---------------------------------------------------------------------------
// ELL adjacency build
// ---------------------------------------------------------------------------
__global__ void ell_build(const float* __restrict__ adj0, const float* __restrict__ adj1,
                          int* __restrict__ cols, float* __restrict__ vals,
                          int* __restrict__ cnt) {
    int br = blockIdx.y, n = blockIdx.x, tid = threadIdx.x;
    const float* row = (br ? adj1 : adj0) + (size_t)n * kN;
    __shared__ int sh[128];
    int c = 0;
    for (int m = tid; m < kN; m += 128) if (row[m] > 0.f) c++;
    sh[tid] = c;
    __syncthreads();
    int off = 0;
    for (int i = 0; i < tid; i++) off += sh[i];
    size_t base = (size_t)(br * kN + n) * 128;
    int pos = off;
    for (int m = tid; m < kN; m += 128) {
        float v = row[m];
        if (v > 0.f) {
            if (pos < 128) { cols[base + pos] = m; vals[base + pos] = v; }
            pos++;
        }
    }
    if (tid == 127) cnt[br * kN + n] = min(off + c, 128);
}

// ---------------------------------------------------------------------------
// Relation aggregator
// ---------------------------------------------------------------------------
__global__ void rel_agg_kernel(const float* __restrict__ ra0, const float* __restrict__ ra1,
                               const float* __restrict__ rel0, const float* __restrict__ rel1,
                               float* __restrict__ outp) {
    int br = blockIdx.y, n = blockIdx.x, d = threadIdx.x;
    const float* row = (br ? ra1 : ra0) + (size_t)n * kR;
    const float* rel = br ? rel1 : rel0;
    __shared__ float sh[128];
    float acc = 0.f, rs = 0.f;
    for (int r0 = 0; r0 < kR; r0 += 128) {
        int r = r0 + d;
        sh[d] = (r < kR) ? row[r] : 0.f;
        __syncthreads();
        int lim = min(128, kR - r0);
        for (int j = 0; j < lim; j++) {
            float v = sh[j];
            if (v != 0.f) { rs += v; acc += v * rel[(size_t)(r0 + j) * 128 + d]; }
        }
        __syncthreads();
    }
    outp[((size_t)br * kN + n) * 128 + d] = acc / rs;
}

// ---------------------------------------------------------------------------
// Tiled GEMM with packed fma.rn.f32x2
//  C[M,NC] = A[M,K] @ B ; mode 0: B[K,ldb] (seg>0: stacked 128x128 head mats)
//  mode 2: B[NC,K] row-major (C = A @ B^T)
//  BM=128 BN=64 BK=32, 128 threads, 8x8 regs (as 8x4 f32x2 pairs)
// ---------------------------------------------------------------------------
__global__ __launch_bounds__(128)
void gemm_tiled(const float* __restrict__ A0, const float* __restrict__ A1, const float* __restrict__ A2,
                const float* __restrict__ B0, const float* __restrict__ B1, const float* __restrict__ B2,
                float* __restrict__ C0, float* __restrict__ C1, float* __restrict__ C2,
                int M, int K, int lda, int ldb, int ldc, int mode, int seg) {
    __shared__ float2 As2[32][130];   // duplicated pairs (a,a)
    __shared__ float  Bs[32][68];
    const float* A = blockIdx.z == 0 ? A0 : (blockIdx.z == 1 ? A1 : A2);
    const float* B = blockIdx.z == 0 ? B0 : (blockIdx.z == 1 ? B1 : B2);
    float* C       = blockIdx.z == 0 ? C0 : (blockIdx.z == 1 ? C1 : C2);
    int m0 = blockIdx.x * 128, n0 = blockIdx.y * 64;
    int tid = threadIdx.x;
    int tx = tid & 7, ty = tid >> 3;
    const float* Bp; int bcol0;
    if (mode == 0 && seg > 0) { Bp = B + (size_t)(n0 >> 7) * seg; bcol0 = n0 & 127; }
    else { Bp = B; bcol0 = n0; }

    unsigned long long acc[8][4];
    #pragma unroll
    for (int i = 0; i < 8; i++)
        #pragma unroll
        for (int j = 0; j < 4; j++) acc[i][j] = 0ull;

    for (int k0 = 0; k0 < K; k0 += 32) {
        #pragma unroll
        for (int i = 0; i < 8; i++) {
            int idx = i * 128 + tid;
            int r = idx >> 3, c = idx & 7;
            int gr = m0 + r;
            float4 v = make_float4(0.f, 0.f, 0.f, 0.f);
            if (gr < M) v = *(const float4*)(A + (size_t)gr * lda + k0 + 4 * c);
            As2[4 * c + 0][r] = make_float2(v.x, v.x);
            As2[4 * c + 1][r] = make_float2(v.y, v.y);
            As2[4 * c + 2][r] = make_float2(v.z, v.z);
            As2[4 * c + 3][r] = make_float2(v.w, v.w);
        }
        if (mode == 0) {
            #pragma unroll
            for (int i = 0; i < 4; i++) {
                int idx = i * 128 + tid;
                int k = idx >> 4, c = idx & 15;
                float4 v = *(const float4*)(Bp + (size_t)(k0 + k) * ldb + bcol0 + 4 * c);
                Bs[k][4 * c + 0] = v.x; Bs[k][4 * c + 1] = v.y;
                Bs[k][4 * c + 2] = v.z; Bs[k][4 * c + 3] = v.w;
            }
        } else {
            #pragma unroll
            for (int i = 0; i < 4; i++) {
                int idx = i * 128 + tid;
                int n = idx >> 3, c = idx & 7;
                float4 v = *(const float4*)(Bp + (size_t)(bcol0 + n) * ldb + k0 + 4 * c);
                Bs[4 * c + 0][n] = v.x; Bs[4 * c + 1][n] = v.y;
                Bs[4 * c + 2][n] = v.z; Bs[4 * c + 3][n] = v.w;
            }
        }
        __syncthreads();
        #pragma unroll
        for (int k = 0; k < 32; k++) {
            unsigned long long a[8], b[4];
            const unsigned long long* ar = (const unsigned long long*)&As2[k][ty * 8];
            const unsigned long long* brp = (const unsigned long long*)&Bs[k][tx * 8];
            #pragma unroll
            for (int i = 0; i < 8; i += 2) {
                ulonglong2 t = *(const ulonglong2*)&ar[i];
                a[i] = t.x; a[i + 1] = t.y;
            }
            {
                ulonglong2 t0 = *(const ulonglong2*)&brp[0];
                ulonglong2 t1 = *(const ulonglong2*)&brp[2];
                b[0] = t0.x; b[1] = t0.y; b[2] = t1.x; b[3] = t1.y;
            }
            #pragma unroll
            for (int i = 0; i < 8; i++)
                #pragma unroll
                for (int j = 0; j < 4; j++)
                    asm("fma.rn.f32x2 %0, %1, %2, %0;"
                        : "+l"(acc[i][j]) : "l"(a[i]), "l"(b[j]));
        }
        __syncthreads();
    }
    #pragma unroll
    for (int i = 0; i < 8; i++) {
        int gr = m0 + ty * 8 + i;
        if (gr < M) {
            float2 p0 = *(float2*)&acc[i][0];
            float2 p1 = *(float2*)&acc[i][1];
            float2 p2 = *(float2*)&acc[i][2];
            float2 p3 = *(float2*)&acc[i][3];
            *(float4*)(C + (size_t)gr * ldc + n0 + tx * 8)     = make_float4(p0.x, p0.y, p1.x, p1.y);
            *(float4*)(C + (size_t)gr * ldc + n0 + tx * 8 + 4) = make_float4(p2.x, p2.y, p3.x, p3.y);
        }
    }
}

// ---------------------------------------------------------------------------
// GAT attention scores; Hc layout [br][n][256]
// ---------------------------------------------------------------------------
__global__ void compute_esed(const float* __restrict__ Hc, const float* __restrict__ asrc,
                             const float* __restrict__ adst,
                             float* __restrict__ es, float* __restrict__ ed) {
    int br = blockIdx.y, n = blockIdx.x, d = threadIdx.x;
    const float* hrow = Hc + ((size_t)br * kN + n) * 256;
    float h0 = hrow[d], h1 = hrow[128 + d];
    float v;
    v = brsum128(h0 * asrc[d]);        if (d == 0) es[(br * 2 + 0) * kN + n] = v;
    v = brsum128(h1 * asrc[128 + d]);  if (d == 0) es[(br * 2 + 1) * kN + n] = v;
    v = brsum128(h0 * adst[d]);        if (d == 0) ed[(br * 2 + 0) * kN + n] = v;
    v = brsum128(h1 * adst[128 + d]);  if (d == 0) ed[(br * 2 + 1) * kN + n] = v;
}

// ---------------------------------------------------------------------------
// GAT aggregation + head mean + elu + normalize; writes into seq slot
// ---------------------------------------------------------------------------
__global__ void gat_attn(const float* __restrict__ Hc, const float* __restrict__ es,
                         const float* __restrict__ ed, const int* __restrict__ cols,
                         const int* __restrict__ cnt, float* __restrict__ seq, int slot) {
    int br = blockIdx.y, n = blockIdx.x, tid = threadIdx.x;
    int rb = br * kN + n;
    int c = cnt[rb];
    size_t base = (size_t)rb * 128;
    __shared__ int csh[128];
    __shared__ float wsh[2][128];
    if (tid < c) csh[tid] = cols[base + tid];
    __syncthreads();
    #pragma unroll
    for (int h = 0; h < 2; h++) {
        float esn = es[(br * 2 + h) * kN + n];
        const float* edh = ed + (size_t)(br * 2 + h) * kN;
        float z = -1e30f;
        if (tid < c) {
            z = esn + edh[csh[tid]];
            z = z > 0.f ? z : 0.2f * z;
        }
        float mx = brmax128(z);
        float ex = (tid < c) ? expf(z - mx) : 0.f;
        float se = brsum128(ex);
        if (tid < c) wsh[h][tid] = ex / se;
    }
    __syncthreads();
    const float* Hb = Hc + (size_t)br * kN * 256;
    float a0 = 0.f, a1 = 0.f;
    for (int j = 0; j < c; j++) {
        size_t ro = (size_t)csh[j] * 256 + tid;
        a0 += wsh[0][j] * Hb[ro];
        a1 += wsh[1][j] * Hb[ro + 128];
    }
    float acc = 0.5f * (a0 + a1);
    acc = acc > 0.f ? acc : expm1f(acc);
    float nrm = sqrtf(brsum128(acc * acc));
    seq[(size_t)rb * 384 + slot * 128 + tid] = acc / fmaxf(nrm, 1e-12f);
}

// ---------------------------------------------------------------------------
// copy ent into seq slot 0
// ---------------------------------------------------------------------------
__global__ void copy_ent(const float* __restrict__ e0, const float* __restrict__ e1,
                         float* __restrict__ seq) {
    int br = blockIdx.y, n = blockIdx.x, d = threadIdx.x;
    const float* ent = br ? e1 : e0;
    seq[((size_t)br * kN + n) * 384 + d] = ent[(size_t)n * 128 + d];
}

// ---------------------------------------------------------------------------
// Per-node MHA (L=3, H=2, D=128)
// ---------------------------------------------------------------------------
__global__ void mha_attn(const float* __restrict__ Q, const float* __restrict__ Kb,
                         const float* __restrict__ V, float* __restrict__ OC) {
    int n = blockIdx.x, tid = threadIdx.x;
    __shared__ float q[3][256], k[3][256], v[3][256];
    __shared__ float att[2][3][3];
    size_t base = (size_t)n * 3 * 256;
    for (int idx = tid; idx < 768; idx += 128) {
        int l = idx >> 8, j = idx & 255;
        q[l][j] = Q[base + (size_t)l * 256 + j];
        k[l][j] = Kb[base + (size_t)l * 256 + j];
        v[l][j] = V[base + (size_t)l * 256 + j];
    }
    __syncthreads();
    int wid = tid >> 5, lane = tid & 31;
    const float scale = 0.08838834764831845f;
    for (int t = wid; t < 18; t += 4) {
        int h = t / 9, l = (t % 9) / 3, m = t % 3;
        float s = 0.f;
        for (int d = lane; d < 128; d += 32) s += q[l][h * 128 + d] * k[m][h * 128 + d];
        #pragma unroll
        for (int o = 16; o > 0; o >>= 1) s += __shfl_down_sync(0xffffffffu, s, o);
        if (lane == 0) att[h][l][m] = s * scale;
    }
    __syncthreads();
    if (tid < 6) {
        int h = tid / 3, l = tid % 3;
        float m0 = att[h][l][0], m1 = att[h][l][1], m2 = att[h][l][2];
        float mx = fmaxf(m0, fmaxf(m1, m2));
        float e0 = expf(m0 - mx), e1 = expf(m1 - mx), e2 = expf(m2 - mx);
        float ss = e0 + e1 + e2;
        att[h][l][0] = e0 / ss; att[h][l][1] = e1 / ss; att[h][l][2] = e2 / ss;
    }
    __syncthreads();
    int d = tid;
    #pragma unroll
    for (int h = 0; h < 2; h++) {
        #pragma unroll
        for (int l = 0; l < 3; l++) {
            float o = att[h][l][0] * v[0][h * 128 + d]
                    + att[h][l][1] * v[1][h * 128 + d]
                    + att[h][l][2] * v[2][h * 128 + d];
            OC[base + (size_t)l * 256 + h * 128 + d] = o;
        }
    }
}

// ---------------------------------------------------------------------------
// MHA epilogue: residual + LN + mean over L
// ---------------------------------------------------------------------------
__global__ void mha_epilogue(const float* __restrict__ FCO, const float* __restrict__ seq,
                             const float* __restrict__ g, const float* __restrict__ b,
                             const float* __restrict__ relagg, float* __restrict__ out) {
    int br = blockIdx.y, n = blockIdx.x, d = threadIdx.x;
    size_t rb = (size_t)br * kN + n;
    float accmean = 0.f;
    for (int l = 0; l < 3; l++) {
        size_t idx = rb * 384 + l * 128 + d;
        float o = FCO[idx] + seq[idx];
        float mu = brsum128(o) * (1.f / 128.f);
        float c = o - mu;
        float var = brsum128(c * c) * (1.f / 128.f);
        accmean += g[d] * c * rsqrtf(var + 1e-6f) + b[d];
    }
    float* ob = out + (size_t)br * kN * 256;
    ob[(size_t)n * 256 + d] = accmean * (1.f / 3.f);
    ob[(size_t)n * 256 + 128 + d] = relagg[rb * 128 + d];
}

// ---------------------------------------------------------------------------
// Hyperbolic ops
// ---------------------------------------------------------------------------
// t1 = logmap0(proj(expmap0(ent)))
__global__ void k_init(const float* __restrict__ e0, const float* __restrict__ e1,
                       float* __restrict__ t1) {
    int br = blockIdx.y, n = blockIdx.x, d = threadIdx.x;
    const float* in = br ? e1 : e0;
    float u = in[(size_t)n * 128 + d];
    float nn = fmaxf(sqrtf(brsum128(u * u)), 1e-15f);
    float p = tanhf(nn) * u / nn;
    float pn = fmaxf(sqrtf(brsum128(p * p)), 1e-15f);
    if (pn > MAXN) p *= MAXN / pn;
    float pn2 = fmaxf(sqrtf(brsum128(p * p)), 1e-15f);
    t1[((size_t)br * kN + n) * 128 + d] = atanhf(fminf(pn2, 1.f - 1e-7f)) * p / pn2;
}

// both biases: bb[i][0..127]=proj(expmap0(b_i)), bb[i][128]=||.||^2
__global__ void k_bias(const float* __restrict__ b, float* __restrict__ bb) {
    int i = blockIdx.x, d = threadIdx.x;
    float u = b[i * 128 + d];
    float nn = fmaxf(sqrtf(brsum128(u * u)), 1e-15f);
    float p = tanhf(nn) * u / nn;
    float pn = fmaxf(sqrtf(brsum128(p * p)), 1e-15f);
    if (pn > MAXN) p *= MAXN / pn;
    float y2 = brsum128(p * p);
    bb[i * 132 + d] = p;
    if (d == 0) bb[i * 132 + 128] = y2;
}

// U -> logmap0(proj(mobius_add(proj(expmap0(U)), bb)))
__global__ void k_hyplinear(const float* __restrict__ U, const float* __restrict__ bb,
                            float* __restrict__ outp) {
    int n = blockIdx.x, d = threadIdx.x;
    float u = U[(size_t)n * 128 + d];
    float nn = fmaxf(sqrtf(brsum128(u * u)), 1e-15f);
    float x = tanhf(nn) * u / nn;
    float xn = fmaxf(sqrtf(brsum128(x * x)), 1e-15f);
    if (xn > MAXN) x *= MAXN / xn;
    float y = bb[d];
    float y2 = bb[128];
    float x2 = brsum128(x * x);
    float xy = brsum128(x * y);
    float num = (1.f + 2.f * xy + y2) * x + (1.f - x2) * y;
    float den = fmaxf(1.f + 2.f * xy + x2 * y2, 1e-15f);
    float h = num / den;
    float hn = fmaxf(sqrtf(brsum128(h * h)), 1e-15f);
    if (hn > MAXN) h *= MAXN / hn;
    float hn2 = fmaxf(sqrtf(brsum128(h * h)), 1e-15f);
    outp[(size_t)n * 128 + d] = atanhf(fminf(hn2, 1.f - 1e-7f)) * h / hn2;
}

// spmm + hypact + logmap0 fused:
// agg = adj @ X; t1 = logmap0(proj(expmap0(relu(logmap0(proj(expmap0(agg)))))))
__global__ void spmm_hypact(const int* __restrict__ cols, const float* __restrict__ vals,
                            const int* __restrict__ cnt, const float* __restrict__ X,
                            float* __restrict__ t1) {
    int br = blockIdx.y, n = blockIdx.x, tid = threadIdx.x;
    int rb = br * kN + n;
    int c = cnt[rb];
    size_t base = (size_t)rb * 128;
    __shared__ int csh[128];
    __shared__ float vsh[128];
    if (tid < c) { csh[tid] = cols[base + tid]; vsh[tid] = vals[base + tid]; }
    __syncthreads();
    const float* Xb = X + (size_t)br * kN * 128;
    float u = 0.f;
    for (int j = 0; j < c; j++)
        u += vsh[j] * Xb[(size_t)csh[j] * 128 + tid];
    // hypact chain
    float nn = fmaxf(sqrtf(brsum128(u * u)), 1e-15f);
    float x = tanhf(nn) * u / nn;
    float xn = fmaxf(sqrtf(brsum128(x * x)), 1e-15f);
    if (xn > MAXN) x *= MAXN / xn;
    float n2 = fmaxf(sqrtf(brsum128(x * x)), 1e-15f);
    float l = atanhf(fminf(n2, 1.f - 1e-7f)) * x / n2;
    float r = fmaxf(l, 0.f);
    float n3 = fmaxf(sqrtf(brsum128(r * r)), 1e-15f);
    float y = tanhf(n3) * r / n3;
    float yn = fmaxf(sqrtf(brsum128(y * y)), 1e-15f);
    if (yn > MAXN) y *= MAXN / yn;
    // trailing logmap0 (next iter's input / finish's input)
    float yn2 = fmaxf(sqrtf(brsum128(y * y)), 1e-15f);
    t1[base + tid] = atanhf(fminf(yn2, 1.f - 1e-7f)) * y / yn2;
}

// out_hyp = ent + t1 ; concat relagg
__global__ void k_finish(const float* __restrict__ t1, const float* __restrict__ e0,
                         const float* __restrict__ e1, const float* __restrict__ relagg,
                         float* __restrict__ out) {
    int br = blockIdx.y, n = blockIdx.x, d = threadIdx.x;
    size_t rb = (size_t)br * kN + n;
    const float* ent = br ? e1 : e0;
    float* ob = out + (size_t)(2 + br) * kN * 256;
    ob[(size_t)n * 256 + d] = ent[(size_t)n * 128 + d] + t1[rb * 128 + d];
    ob[(size_t)n * 256 + 128 + d] = relagg[rb * 128 + d];
}

// ---------------------------------------------------------------------------
// Host side
// ---------------------------------------------------------------------------
extern "C" void kernel_launch(void* const* d_in, const int* in_sizes, int n_in,
                              void* d_out, int out_size) {
    (void)in_sizes; (void)n_in; (void)out_size;
    const float* ent_sr     = (const float*)d_in[0];
    const float* ent_tg     = (const float*)d_in[1];
    const float* rel_sr     = (const float*)d_in[2];
    const float* rel_tg     = (const float*)d_in[3];
    const float* adj_sr     = (const float*)d_in[4];
    const float* adj_tg     = (const float*)d_in[5];
    const float* rel_adj_sr = (const float*)d_in[6];
    const float* rel_adj_tg = (const float*)d_in[7];
    const float* gat_W      = (const float*)d_in[8];
    const float* gat_a_src  = (const float*)d_in[9];
    const float* gat_a_dst  = (const float*)d_in[10];
    const float* Wq         = (const float*)d_in[11];
    const float* Wk         = (const float*)d_in[12];
    const float* Wv         = (const float*)d_in[13];
    const float* Wfc        = (const float*)d_in[14];
    const float* ln_g       = (const float*)d_in[15];
    const float* ln_b       = (const float*)d_in[16];
    const float* hgc_W      = (const float*)d_in[17];
    const float* hgc_b      = (const float*)d_in[18];
    float* out = (float*)d_out;

    float* FP; int* IP;
    cudaGetSymbolAddress((void**)&FP, g_fpool);
    cudaGetSymbolAddress((void**)&IP, g_ipool);

    float* relagg = FP + OF_RELAGG;
    float* Hc   = FP + OF_HC;
    float* t3   = FP + OF_T3;
    float* es   = FP + OF_ES;
    float* ed   = FP + OF_ED;
    float* seq  = FP + OF_SEQ;
    float* qb   = FP + OF_QB;
    float* kb   = FP + OF_KB;
    float* vb   = FP + OF_VB;
    float* oc   = FP + OF_OC;
    float* fco  = FP + OF_FCO;
    float* t1   = FP + OF_T1;
    float* t2   = FP + OF_T2;
    float* bb   = FP + OF_BB;
    float* vals = FP + OF_VALS;
    int* cols = IP + IO_COLS;
    int* cnt  = IP + IO_CNT;

    dim3 gN2(kN, 2);

    ell_build<<<gN2, 128>>>(adj_sr, adj_tg, cols, vals, cnt);
    rel_agg_kernel<<<gN2, 128>>>(rel_adj_sr, rel_adj_tg, rel_sr, rel_tg, relagg);
    k_bias<<<2, 128>>>(hgc_b, bb);
    copy_ent<<<gN2, 128>>>(ent_sr, ent_tg, seq);

    float* Hc0 = Hc;
    float* Hc1 = Hc + (size_t)kN * 256;
    float* seq1 = seq + (size_t)kN * 384;

    // ---- GAT layer 0 ----
    gemm_tiled<<<dim3(47, 4, 2), 128>>>(ent_sr, ent_tg, ent_tg,
                                        gat_W, gat_W, gat_W,
                                        Hc0, Hc1, Hc1,
                                        kN, 128, 128, 128, 256, 0, DD);
    compute_esed<<<gN2, 128>>>(Hc, gat_a_src, gat_a_dst, es, ed);
    gat_attn<<<gN2, 128>>>(Hc, es, ed, cols, cnt, seq, 1);

    // ---- GAT layer 1 (A = seq slot 1, lda=384) ----
    gemm_tiled<<<dim3(47, 4, 2), 128>>>(seq + 128, seq1 + 128, seq1 + 128,
                                        gat_W + 2 * DD, gat_W + 2 * DD, gat_W + 2 * DD,
                                        Hc0, Hc1, Hc1,
                                        kN, 128, 384, 128, 256, 0, DD);
    compute_esed<<<gN2, 128>>>(Hc, gat_a_src + 256, gat_a_dst + 256, es, ed);
    gat_attn<<<gN2, 128>>>(Hc, es, ed, cols, cnt, seq, 2);

    // ---- MHA over [x0,h1,h2] ----
    gemm_tiled<<<dim3(282, 4, 3), 128>>>(seq, seq, seq, Wq, Wk, Wv, qb, kb, vb,
                                         36000, 128, 128, 256, 256, 0, 0);
    mha_attn<<<12000, 128>>>(qb, kb, vb, oc);
    gemm_tiled<<<dim3(282, 2, 1), 128>>>(oc, oc, oc, Wfc, Wfc, Wfc, fco, fco, fco,
                                         36000, 256, 256, 128, 128, 0, 0);
    mha_epilogue<<<gN2, 128>>>(fco, seq, ln_g, ln_b, relagg, out);

    // ---- Hyperbolic encoder ----
    k_init<<<gN2, 128>>>(ent_sr, ent_tg, t1);
    for (int i = 0; i < 2; i++) {
        gemm_tiled<<<dim3(94, 2, 1), 128>>>(t1, t1, t1,
                                            hgc_W + i * DD, hgc_W + i * DD, hgc_W + i * DD,
                                            t2, t2, t2,
                                            12000, 128, 128, 128, 128, 2, 0);   // x @ W.T
        k_hyplinear<<<12000, 128>>>(t2, bb + i * 132, t3);
        spmm_hypact<<<gN2, 128>>>(cols, vals, cnt, t3, t1);
    }
    k_finish<<<gN2, 128>>>(t1, ent_sr, ent_tg, relagg, out);
}

// round 5
// speedup vs baseline: 1.0970x; 1.0970x over previous
#include <cuda_runtime.h>
#include <cuda_bf16.h>
#include <math.h>
#include <stdint.h>

// ---------------------------------------------------------------------------
// Problem constants
// ---------------------------------------------------------------------------
#define kN   6000
#define kR   1000
#define MAXN 0.996f
#define DD   (128*128)

// ---------------------------------------------------------------------------
// Static scratch pools (element offsets)
// ---------------------------------------------------------------------------
#define OF_RELAGG  0            // 2 x 768000
#define OF_HC      1536000      // 2 x 1536000  ([br][n][256])
#define OF_T3      4608000      // 1536000
#define OF_ES      7680000      // 24000
#define OF_ED      7704000      // 24000
#define OF_SEQ     7728000      // 4608000  ([br*6000+n][3][128])
#define OF_QB      12336000     // 9216000
#define OF_KB      21552000     // 9216000
#define OF_VB      30768000     // 9216000
#define OF_OC      39984000     // 9216000
#define OF_FCO     49200000     // 4608000
#define OF_T1      53808000     // 1536000
#define OF_T2      55344000     // 1536000
#define OF_BB      58416000     // 2 x 132
#define OF_VALS    58420000     // 1536000
__device__ float g_fpool[60000000];

#define IO_COLS 0               // 1536000
#define IO_CNT  1536000         // 12000
__device__ int g_ipool[1549000];

// ---------------------------------------------------------------------------
// Block reductions (blockDim.x == 128)
// ---------------------------------------------------------------------------
__device__ __forceinline__ float brsum128(float v) {
    __shared__ float sh[4];
    #pragma unroll
    for (int o = 16; o > 0; o >>= 1) v += __shfl_down_sync(0xffffffffu, v, o);
    __syncthreads();
    if ((threadIdx.x & 31) == 0) sh[threadIdx.x >> 5] = v;
    __syncthreads();
    return sh[0] + sh[1] + sh[2] + sh[3];
}

__device__ __forceinline__ float brmax128(float v) {
    __shared__ float shm[4];
    #pragma unroll
    for (int o = 16; o > 0; o >>= 1) v = fmaxf(v, __shfl_down_sync(0xffffffffu, v, o));
    __syncthreads();
    if ((threadIdx.x & 31) == 0) shm[threadIdx.x >> 5] = v;
    __syncthreads();
    return fmaxf(fmaxf(shm[0], shm[1]), fmaxf(shm[2], shm[3]));
}

// ---------------------------------------------------------------------------
// ELL adjacency build
// ---------------------------------------------------------------------------
__global__ void ell_build(const float* __restrict__ adj0, const float* __restrict__ adj1,
                          int* __restrict__ cols, float* __restrict__ vals,
                          int* __restrict__ cnt) {
    int br = blockIdx.y, n = blockIdx.x, tid = threadIdx.x;
    const float* row = (br ? adj1 : adj0) + (size_t)n * kN;
    __shared__ int sh[128];
    int c = 0;
    for (int m = tid; m < kN; m += 128) if (row[m] > 0.f) c++;
    sh[tid] = c;
    __syncthreads();
    int off = 0;
    for (int i = 0; i < tid; i++) off += sh[i];
    size_t base = (size_t)(br * kN + n) * 128;
    int pos = off;
    for (int m = tid; m < kN; m += 128) {
        float v = row[m];
        if (v > 0.f) {
            if (pos < 128) { cols[base + pos] = m; vals[base + pos] = v; }
            pos++;
        }
    }
    if (tid == 127) cnt[br * kN + n] = min(off + c, 128);
}

// ---------------------------------------------------------------------------
// Relation aggregator
// ---------------------------------------------------------------------------
__global__ void rel_agg_kernel(const float* __restrict__ ra0, const float* __restrict__ ra1,
                               const float* __restrict__ rel0, const float* __restrict__ rel1,
                               float* __restrict__ outp) {
    int br = blockIdx.y, n = blockIdx.x, d = threadIdx.x;
    const float* row = (br ? ra1 : ra0) + (size_t)n * kR;
    const float* rel = br ? rel1 : rel0;
    __shared__ float sh[128];
    float acc = 0.f, rs = 0.f;
    for (int r0 = 0; r0 < kR; r0 += 128) {
        int r = r0 + d;
        sh[d] = (r < kR) ? row[r] : 0.f;
        __syncthreads();
        int lim = min(128, kR - r0);
        for (int j = 0; j < lim; j++) {
            float v = sh[j];
            if (v != 0.f) { rs += v; acc += v * rel[(size_t)(r0 + j) * 128 + d]; }
        }
        __syncthreads();
    }
    outp[((size_t)br * kN + n) * 128 + d] = acc / rs;
}

// ---------------------------------------------------------------------------
// Tiled GEMM (plain FFMA, R2-proven): C[M,NC] = A[M,K] @ B
//  mode 0: B[K,ldb] (seg>0: stacked 128x128 head matrices)
//  mode 2: B[NC,ldb=K] row-major (C = A @ B^T)
//  BM=128 BN=64 BK=32, 128 threads, 8x8 register tile
// ---------------------------------------------------------------------------
__global__ __launch_bounds__(128)
void gemm_tiled(const float* __restrict__ A0, const float* __restrict__ A1, const float* __restrict__ A2,
                const float* __restrict__ B0, const float* __restrict__ B1, const float* __restrict__ B2,
                float* __restrict__ C0, float* __restrict__ C1, float* __restrict__ C2,
                int M, int K, int lda, int ldb, int ldc, int mode, int seg) {
    __shared__ float As[32][132];
    __shared__ float Bs[32][68];
    const float* A = blockIdx.z == 0 ? A0 : (blockIdx.z == 1 ? A1 : A2);
    const float* B = blockIdx.z == 0 ? B0 : (blockIdx.z == 1 ? B1 : B2);
    float* C       = blockIdx.z == 0 ? C0 : (blockIdx.z == 1 ? C1 : C2);
    int m0 = blockIdx.x * 128, n0 = blockIdx.y * 64;
    int tid = threadIdx.x;
    int tx = tid & 7, ty = tid >> 3;
    const float* Bp; int bcol0;
    if (mode == 0 && seg > 0) { Bp = B + (size_t)(n0 >> 7) * seg; bcol0 = n0 & 127; }
    else { Bp = B; bcol0 = n0; }

    float acc[8][8];
    #pragma unroll
    for (int i = 0; i < 8; i++)
        #pragma unroll
        for (int j = 0; j < 8; j++) acc[i][j] = 0.f;

    for (int k0 = 0; k0 < K; k0 += 32) {
        #pragma unroll
        for (int i = 0; i < 8; i++) {
            int idx = i * 128 + tid;
            int r = idx >> 3, c = idx & 7;
            int gr = m0 + r;
            float4 v = make_float4(0.f, 0.f, 0.f, 0.f);
            if (gr < M) v = *(const float4*)(A + (size_t)gr * lda + k0 + 4 * c);
            As[4 * c + 0][r] = v.x; As[4 * c + 1][r] = v.y;
            As[4 * c + 2][r] = v.z; As[4 * c + 3][r] = v.w;
        }
        if (mode == 0) {
            #pragma unroll
            for (int i = 0; i < 4; i++) {
                int idx = i * 128 + tid;
                int k = idx >> 4, c = idx & 15;
                float4 v = *(const float4*)(Bp + (size_t)(k0 + k) * ldb + bcol0 + 4 * c);
                Bs[k][4 * c + 0] = v.x; Bs[k][4 * c + 1] = v.y;
                Bs[k][4 * c + 2] = v.z; Bs[k][4 * c + 3] = v.w;
            }
        } else {
            #pragma unroll
            for (int i = 0; i < 4; i++) {
                int idx = i * 128 + tid;
                int n = idx >> 3, c = idx & 7;
                float4 v = *(const float4*)(Bp + (size_t)(bcol0 + n) * ldb + k0 + 4 * c);
                Bs[4 * c + 0][n] = v.x; Bs[4 * c + 1][n] = v.y;
                Bs[4 * c + 2][n] = v.z; Bs[4 * c + 3][n] = v.w;
            }
        }
        __syncthreads();
        #pragma unroll
        for (int k = 0; k < 32; k++) {
            float a[8], b[8];
            *(float4*)&a[0] = *(const float4*)&As[k][ty * 8];
            *(float4*)&a[4] = *(const float4*)&As[k][ty * 8 + 4];
            *(float4*)&b[0] = *(const float4*)&Bs[k][tx * 8];
            *(float4*)&b[4] = *(const float4*)&Bs[k][tx * 8 + 4];
            #pragma unroll
            for (int i = 0; i < 8; i++)
                #pragma unroll
                for (int j = 0; j < 8; j++)
                    acc[i][j] = fmaf(a[i], b[j], acc[i][j]);
        }
        __syncthreads();
    }
    #pragma unroll
    for (int i = 0; i < 8; i++) {
        int gr = m0 + ty * 8 + i;
        if (gr < M) {
            #pragma unroll
            for (int j = 0; j < 8; j += 4) {
                float4 v = make_float4(acc[i][j], acc[i][j + 1], acc[i][j + 2], acc[i][j + 3]);
                *(float4*)(C + (size_t)gr * ldc + n0 + tx * 8 + j) = v;
            }
        }
    }
}

// ---------------------------------------------------------------------------
// GAT attention scores; Hc layout [br][n][256]
// ---------------------------------------------------------------------------
__global__ void compute_esed(const float* __restrict__ Hc, const float* __restrict__ asrc,
                             const float* __restrict__ adst,
                             float* __restrict__ es, float* __restrict__ ed) {
    int br = blockIdx.y, n = blockIdx.x, d = threadIdx.x;
    const float* hrow = Hc + ((size_t)br * kN + n) * 256;
    float h0 = hrow[d], h1 = hrow[128 + d];
    float v;
    v = brsum128(h0 * asrc[d]);        if (d == 0) es[(br * 2 + 0) * kN + n] = v;
    v = brsum128(h1 * asrc[128 + d]);  if (d == 0) es[(br * 2 + 1) * kN + n] = v;
    v = brsum128(h0 * adst[d]);        if (d == 0) ed[(br * 2 + 0) * kN + n] = v;
    v = brsum128(h1 * adst[128 + d]);  if (d == 0) ed[(br * 2 + 1) * kN + n] = v;
}

// ---------------------------------------------------------------------------
// GAT aggregation + head mean + elu + normalize; writes into seq slot
// ---------------------------------------------------------------------------
__global__ void gat_attn(const float* __restrict__ Hc, const float* __restrict__ es,
                         const float* __restrict__ ed, const int* __restrict__ cols,
                         const int* __restrict__ cnt, float* __restrict__ seq, int slot) {
    int br = blockIdx.y, n = blockIdx.x, tid = threadIdx.x;
    int rb = br * kN + n;
    int c = cnt[rb];
    size_t base = (size_t)rb * 128;
    __shared__ int csh[128];
    __shared__ float wsh[2][128];
    if (tid < c) csh[tid] = cols[base + tid];
    __syncthreads();
    #pragma unroll
    for (int h = 0; h < 2; h++) {
        float esn = es[(br * 2 + h) * kN + n];
        const float* edh = ed + (size_t)(br * 2 + h) * kN;
        float z = -1e30f;
        if (tid < c) {
            z = esn + edh[csh[tid]];
            z = z > 0.f ? z : 0.2f * z;
        }
        float mx = brmax128(z);
        float ex = (tid < c) ? expf(z - mx) : 0.f;
        float se = brsum128(ex);
        if (tid < c) wsh[h][tid] = ex / se;
    }
    __syncthreads();
    const float* Hb = Hc + (size_t)br * kN * 256;
    float a0 = 0.f, a1 = 0.f;
    for (int j = 0; j < c; j++) {
        size_t ro = (size_t)csh[j] * 256 + tid;
        a0 += wsh[0][j] * Hb[ro];
        a1 += wsh[1][j] * Hb[ro + 128];
    }
    float acc = 0.5f * (a0 + a1);
    acc = acc > 0.f ? acc : expm1f(acc);
    float nrm = sqrtf(brsum128(acc * acc));
    seq[(size_t)rb * 384 + slot * 128 + tid] = acc / fmaxf(nrm, 1e-12f);
}

// ---------------------------------------------------------------------------
// Per-node MHA (L=3, H=2, D=128)
// ---------------------------------------------------------------------------
__global__ void mha_attn(const float* __restrict__ Q, const float* __restrict__ Kb,
                         const float* __restrict__ V, float* __restrict__ OC) {
    int n = blockIdx.x, tid = threadIdx.x;
    __shared__ float q[3][256], k[3][256], v[3][256];
    __shared__ float att[2][3][3];
    size_t base = (size_t)n * 3 * 256;
    for (int idx = tid; idx < 768; idx += 128) {
        int l = idx >> 8, j = idx & 255;
        q[l][j] = Q[base + (size_t)l * 256 + j];
        k[l][j] = Kb[base + (size_t)l * 256 + j];
        v[l][j] = V[base + (size_t)l * 256 + j];
    }
    __syncthreads();
    int wid = tid >> 5, lane = tid & 31;
    const float scale = 0.08838834764831845f;
    for (int t = wid; t < 18; t += 4) {
        int h = t / 9, l = (t % 9) / 3, m = t % 3;
        float s = 0.f;
        for (int d = lane; d < 128; d += 32) s += q[l][h * 128 + d] * k[m][h * 128 + d];
        #pragma unroll
        for (int o = 16; o > 0; o >>= 1) s += __shfl_down_sync(0xffffffffu, s, o);
        if (lane == 0) att[h][l][m] = s * scale;
    }
    __syncthreads();
    if (tid < 6) {
        int h = tid / 3, l = tid % 3;
        float m0 = att[h][l][0], m1 = att[h][l][1], m2 = att[h][l][2];
        float mx = fmaxf(m0, fmaxf(m1, m2));
        float e0 = expf(m0 - mx), e1 = expf(m1 - mx), e2 = expf(m2 - mx);
        float ss = e0 + e1 + e2;
        att[h][l][0] = e0 / ss; att[h][l][1] = e1 / ss; att[h][l][2] = e2 / ss;
    }
    __syncthreads();
    int d = tid;
    #pragma unroll
    for (int h = 0; h < 2; h++) {
        #pragma unroll
        for (int l = 0; l < 3; l++) {
            float o = att[h][l][0] * v[0][h * 128 + d]
                    + att[h][l][1] * v[1][h * 128 + d]
                    + att[h][l][2] * v[2][h * 128 + d];
            OC[base + (size_t)l * 256 + h * 128 + d] = o;
        }
    }
}

// ---------------------------------------------------------------------------
// MHA epilogue: residual + LN + mean over L
// ---------------------------------------------------------------------------
__global__ void mha_epilogue(const float* __restrict__ FCO, const float* __restrict__ seq,
                             const float* __restrict__ g, const float* __restrict__ b,
                             const float* __restrict__ relagg, float* __restrict__ out) {
    int br = blockIdx.y, n = blockIdx.x, d = threadIdx.x;
    size_t rb = (size_t)br * kN + n;
    float accmean = 0.f;
    for (int l = 0; l < 3; l++) {
        size_t idx = rb * 384 + l * 128 + d;
        float o = FCO[idx] + seq[idx];
        float mu = brsum128(o) * (1.f / 128.f);
        float c = o - mu;
        float var = brsum128(c * c) * (1.f / 128.f);
        accmean += g[d] * c * rsqrtf(var + 1e-6f) + b[d];
    }
    float* ob = out + (size_t)br * kN * 256;
    ob[(size_t)n * 256 + d] = accmean * (1.f / 3.f);
    ob[(size_t)n * 256 + 128 + d] = relagg[rb * 128 + d];
}

// ---------------------------------------------------------------------------
// Hyperbolic ops
// ---------------------------------------------------------------------------
// t1 = logmap0(proj(expmap0(ent)))  AND  seq slot0 = ent (merged copy_ent)
__global__ void k_init(const float* __restrict__ e0, const float* __restrict__ e1,
                       float* __restrict__ t1, float* __restrict__ seq) {
    int br = blockIdx.y, n = blockIdx.x, d = threadIdx.x;
    const float* in = br ? e1 : e0;
    float u = in[(size_t)n * 128 + d];
    size_t rb = (size_t)br * kN + n;
    seq[rb * 384 + d] = u;
    float nn = fmaxf(sqrtf(brsum128(u * u)), 1e-15f);
    float p = tanhf(nn) * u / nn;
    float pn = fmaxf(sqrtf(brsum128(p * p)), 1e-15f);
    if (pn > MAXN) p *= MAXN / pn;
    float pn2 = fmaxf(sqrtf(brsum128(p * p)), 1e-15f);
    t1[rb * 128 + d] = atanhf(fminf(pn2, 1.f - 1e-7f)) * p / pn2;
}

// both biases: bb[i][0..127]=proj(expmap0(b_i)), bb[i][128]=||.||^2
__global__ void k_bias(const float* __restrict__ b, float* __restrict__ bb) {
    int i = blockIdx.x, d = threadIdx.x;
    float u = b[i * 128 + d];
    float nn = fmaxf(sqrtf(brsum128(u * u)), 1e-15f);
    float p = tanhf(nn) * u / nn;
    float pn = fmaxf(sqrtf(brsum128(p * p)), 1e-15f);
    if (pn > MAXN) p *= MAXN / pn;
    float y2 = brsum128(p * p);
    bb[i * 132 + d] = p;
    if (d == 0) bb[i * 132 + 128] = y2;
}

// U -> logmap0(proj(mobius_add(proj(expmap0(U)), bb)))
__global__ void k_hyplinear(const float* __restrict__ U, const float* __restrict__ bb,
                            float* __restrict__ outp) {
    int n = blockIdx.x, d = threadIdx.x;
    float u = U[(size_t)n * 128 + d];
    float nn = fmaxf(sqrtf(brsum128(u * u)), 1e-15f);
    float x = tanhf(nn) * u / nn;
    float xn = fmaxf(sqrtf(brsum128(x * x)), 1e-15f);
    if (xn > MAXN) x *= MAXN / xn;
    float y = bb[d];
    float y2 = bb[128];
    float x2 = brsum128(x * x);
    float xy = brsum128(x * y);
    float num = (1.f + 2.f * xy + y2) * x + (1.f - x2) * y;
    float den = fmaxf(1.f + 2.f * xy + x2 * y2, 1e-15f);
    float h = num / den;
    float hn = fmaxf(sqrtf(brsum128(h * h)), 1e-15f);
    if (hn > MAXN) h *= MAXN / hn;
    float hn2 = fmaxf(sqrtf(brsum128(h * h)), 1e-15f);
    outp[(size_t)n * 128 + d] = atanhf(fminf(hn2, 1.f - 1e-7f)) * h / hn2;
}

// spmm + hypact + logmap0 fused
__global__ void spmm_hypact(const int* __restrict__ cols, const float* __restrict__ vals,
                            const int* __restrict__ cnt, const float* __restrict__ X,
                            float* __restrict__ t1) {
    int br = blockIdx.y, n = blockIdx.x, tid = threadIdx.x;
    int rb = br * kN + n;
    int c = cnt[rb];
    size_t base = (size_t)rb * 128;
    __shared__ int csh[128];
    __shared__ float vsh[128];
    if (tid < c) { csh[tid] = cols[base + tid]; vsh[tid] = vals[base + tid]; }
    __syncthreads();
    const float* Xb = X + (size_t)br * kN * 128;
    float u = 0.f;
    for (int j = 0; j < c; j++)
        u += vsh[j] * Xb[(size_t)csh[j] * 128 + tid];
    float nn = fmaxf(sqrtf(brsum128(u * u)), 1e-15f);
    float x = tanhf(nn) * u / nn;
    float xn = fmaxf(sqrtf(brsum128(x * x)), 1e-15f);
    if (xn > MAXN) x *= MAXN / xn;
    float n2 = fmaxf(sqrtf(brsum128(x * x)), 1e-15f);
    float l = atanhf(fminf(n2, 1.f - 1e-7f)) * x / n2;
    float r = fmaxf(l, 0.f);
    float n3 = fmaxf(sqrtf(brsum128(r * r)), 1e-15f);
    float y = tanhf(n3) * r / n3;
    float yn = fmaxf(sqrtf(brsum128(y * y)), 1e-15f);
    if (yn > MAXN) y *= MAXN / yn;
    float yn2 = fmaxf(sqrtf(brsum128(y * y)), 1e-15f);
    t1[base + tid] = atanhf(fminf(yn2, 1.f - 1e-7f)) * y / yn2;
}

// out_hyp = ent + t1 ; concat relagg
__global__ void k_finish(const float* __restrict__ t1, const float* __restrict__ e0,
                         const float* __restrict__ e1, const float* __restrict__ relagg,
                         float* __restrict__ out) {
    int br = blockIdx.y, n = blockIdx.x, d = threadIdx.x;
    size_t rb = (size_t)br * kN + n;
    const float* ent = br ? e1 : e0;
    float* ob = out + (size_t)(2 + br) * kN * 256;
    ob[(size_t)n * 256 + d] = ent[(size_t)n * 128 + d] + t1[rb * 128 + d];
    ob[(size_t)n * 256 + 128 + d] = relagg[rb * 128 + d];
}

// ---------------------------------------------------------------------------
// Host side
// ---------------------------------------------------------------------------
extern "C" void kernel_launch(void* const* d_in, const int* in_sizes, int n_in,
                              void* d_out, int out_size) {
    (void)in_sizes; (void)n_in; (void)out_size;
    const float* ent_sr     = (const float*)d_in[0];
    const float* ent_tg     = (const float*)d_in[1];
    const float* rel_sr     = (const float*)d_in[2];
    const float* rel_tg     = (const float*)d_in[3];
    const float* adj_sr     = (const float*)d_in[4];
    const float* adj_tg     = (const float*)d_in[5];
    const float* rel_adj_sr = (const float*)d_in[6];
    const float* rel_adj_tg = (const float*)d_in[7];
    const float* gat_W      = (const float*)d_in[8];
    const float* gat_a_src  = (const float*)d_in[9];
    const float* gat_a_dst  = (const float*)d_in[10];
    const float* Wq         = (const float*)d_in[11];
    const float* Wk         = (const float*)d_in[12];
    const float* Wv         = (const float*)d_in[13];
    const float* Wfc        = (const float*)d_in[14];
    const float* ln_g       = (const float*)d_in[15];
    const float* ln_b       = (const float*)d_in[16];
    const float* hgc_W      = (const float*)d_in[17];
    const float* hgc_b      = (const float*)d_in[18];
    float* out = (float*)d_out;

    float* FP; int* IP;
    cudaGetSymbolAddress((void**)&FP, g_fpool);
    cudaGetSymbolAddress((void**)&IP, g_ipool);

    float* relagg = FP + OF_RELAGG;
    float* Hc   = FP + OF_HC;
    float* t3   = FP + OF_T3;
    float* es   = FP + OF_ES;
    float* ed   = FP + OF_ED;
    float* seq  = FP + OF_SEQ;
    float* qb   = FP + OF_QB;
    float* kb   = FP + OF_KB;
    float* vb   = FP + OF_VB;
    float* oc   = FP + OF_OC;
    float* fco  = FP + OF_FCO;
    float* t1   = FP + OF_T1;
    float* t2   = FP + OF_T2;
    float* bb   = FP + OF_BB;
    float* vals = FP + OF_VALS;
    int* cols = IP + IO_COLS;
    int* cnt  = IP + IO_CNT;

    dim3 gN2(kN, 2);

    ell_build<<<gN2, 128>>>(adj_sr, adj_tg, cols, vals, cnt);
    rel_agg_kernel<<<gN2, 128>>>(rel_adj_sr, rel_adj_tg, rel_sr, rel_tg, relagg);
    k_bias<<<2, 128>>>(hgc_b, bb);
    k_init<<<gN2, 128>>>(ent_sr, ent_tg, t1, seq);

    float* Hc0 = Hc;
    float* Hc1 = Hc + (size_t)kN * 256;
    float* seq1 = seq + (size_t)kN * 384;

    // ---- GAT layer 0 ----
    gemm_tiled<<<dim3(47, 4, 2), 128>>>(ent_sr, ent_tg, ent_tg,
                                        gat_W, gat_W, gat_W,
                                        Hc0, Hc1, Hc1,
                                        kN, 128, 128, 128, 256, 0, DD);
    compute_esed<<<gN2, 128>>>(Hc, gat_a_src, gat_a_dst, es, ed);
    gat_attn<<<gN2, 128>>>(Hc, es, ed, cols, cnt, seq, 1);

    // ---- GAT layer 1 (A = seq slot 1, lda=384) ----
    gemm_tiled<<<dim3(47, 4, 2), 128>>>(seq + 128, seq1 + 128, seq1 + 128,
                                        gat_W + 2 * DD, gat_W + 2 * DD, gat_W + 2 * DD,
                                        Hc0, Hc1, Hc1,
                                        kN, 128, 384, 128, 256, 0, DD);
    compute_esed<<<gN2, 128>>>(Hc, gat_a_src + 256, gat_a_dst + 256, es, ed);
    gat_attn<<<gN2, 128>>>(Hc, es, ed, cols, cnt, seq, 2);

    // ---- MHA over [x0,h1,h2] ----
    gemm_tiled<<<dim3(282, 4, 3), 128>>>(seq, seq, seq, Wq, Wk, Wv, qb, kb, vb,
                                         36000, 128, 128, 256, 256, 0, 0);
    mha_attn<<<12000, 128>>>(qb, kb, vb, oc);
    gemm_tiled<<<dim3(282, 2, 1), 128>>>(oc, oc, oc, Wfc, Wfc, Wfc, fco, fco, fco,
                                         36000, 256, 256, 128, 128, 0, 0);
    mha_epilogue<<<gN2, 128>>>(fco, seq, ln_g, ln_b, relagg, out);

    // ---- Hyperbolic encoder ----
    for (int i = 0; i < 2; i++) {
        gemm_tiled<<<dim3(94, 2, 1), 128>>>(t1, t1, t1,
                                            hgc_W + i * DD, hgc_W + i * DD, hgc_W + i * DD,
                                            t2, t2, t2,
                                            12000, 128, 128, 128, 128, 2, 0);   // x @ W.T
        k_hyplinear<<<12000, 128>>>(t2, bb + i * 132, t3);
        spmm_hypact<<<gN2, 128>>>(cols, vals, cnt, t3, t1);
    }
    k_finish<<<gN2, 128>>>(t1, ent_sr, ent_tg, relagg, out);
}

// round 17
// speedup vs baseline: 1.2842x; 1.1706x over previous
#include <cuda_runtime.h>
#include <cuda_bf16.h>
#include <math.h>
#include <stdint.h>

// ---------------------------------------------------------------------------
// Problem constants
// ---------------------------------------------------------------------------
#define kN   6000
#define kR   1000
#define MAXN 0.996f
#define DD   (128*128)

// ---------------------------------------------------------------------------
// Static scratch pools (element offsets)
// ---------------------------------------------------------------------------
#define OF_RELAGG  0            // 2 x 768000
#define OF_HC      1536000      // 2 x 1536000  ([br][n][256])
#define OF_T3      4608000      // 1536000
#define OF_ES      7680000      // 24000
#define OF_ED      7704000      // 24000
#define OF_SEQ     7728000      // 4608000  ([br*6000+n][3][128])
#define OF_QB      12336000     // 9216000
#define OF_KB      21552000     // 9216000
#define OF_VB      30768000     // 9216000
#define OF_OC      39984000     // 9216000
#define OF_FCO     49200000     // 4608000
#define OF_T1      53808000     // 1536000
#define OF_T2      55344000     // 1536000
#define OF_BB      58416000     // 2 x 132
#define OF_VALS    58420000     // 1536000
__device__ float g_fpool[60000000];

#define IO_COLS 0               // 1536000
#define IO_CNT  1536000         // 12000
__device__ int g_ipool[1549000];

// bf16 weight pool: hi at [0,229376), lo at [229376, 458752)
//   gat Wt:  seg s=l*2+h at s*16384     (combined [256,128] per layer)
//   Wq/Wk/Wv t: 65536 + j*32768         ([256,128])
//   Wfc t:   163840                     ([128,256])
//   hgc W:   196608 + i*16384           ([128,128])
#define BLO_OFF 229376
__device__ __nv_bfloat16 g_bpool[458752];

// ---------------------------------------------------------------------------
// Block reductions (blockDim.x == 128)
// ---------------------------------------------------------------------------
__device__ __forceinline__ float brsum128(float v) {
    __shared__ float sh[4];
    #pragma unroll
    for (int o = 16; o > 0; o >>= 1) v += __shfl_down_sync(0xffffffffu, v, o);
    __syncthreads();
    if ((threadIdx.x & 31) == 0) sh[threadIdx.x >> 5] = v;
    __syncthreads();
    return sh[0] + sh[1] + sh[2] + sh[3];
}

__device__ __forceinline__ float brmax128(float v) {
    __shared__ float shm[4];
    #pragma unroll
    for (int o = 16; o > 0; o >>= 1) v = fmaxf(v, __shfl_down_sync(0xffffffffu, v, o));
    __syncthreads();
    if ((threadIdx.x & 31) == 0) shm[threadIdx.x >> 5] = v;
    __syncthreads();
    return fmaxf(fmaxf(shm[0], shm[1]), fmaxf(shm[2], shm[3]));
}

// ---------------------------------------------------------------------------
// helpers
// ---------------------------------------------------------------------------
__device__ __forceinline__ uint32_t smem_u32(const void* p) {
    uint32_t a;
    asm("{ .reg .u64 t; cvta.to.shared.u64 t, %1; cvt.u32.u64 %0, t; }" : "=r"(a) : "l"(p));
    return a;
}
__device__ __forceinline__ uint32_t pack_bf2(__nv_bfloat16 a, __nv_bfloat16 b) {
    return (uint32_t)__bfloat16_as_ushort(a) | ((uint32_t)__bfloat16_as_ushort(b) << 16);
}

#define LDMX4(r, addr) \
    asm volatile("ldmatrix.sync.aligned.m8n8.x4.shared.b16 {%0,%1,%2,%3}, [%4];" \
        : "=r"((r)[0]), "=r"((r)[1]), "=r"((r)[2]), "=r"((r)[3]) : "r"(addr))
#define MMA16816(d, a, b0, b1) \
    asm volatile("mma.sync.aligned.m16n8k16.row.col.f32.bf16.bf16.f32 " \
        "{%0,%1,%2,%3}, {%4,%5,%6,%7}, {%8,%9}, {%0,%1,%2,%3};" \
        : "+f"((d)[0]), "+f"((d)[1]), "+f"((d)[2]), "+f"((d)[3]) \
        : "r"((a)[0]), "r"((a)[1]), "r"((a)[2]), "r"((a)[3]), "r"(b0), "r"(b1))

// ---------------------------------------------------------------------------
// Weight convert/transpose/split to bf16 hi/lo. grid (128, 10), 256 threads.
// ---------------------------------------------------------------------------
__global__ void conv_w(const float* __restrict__ gat_W, const float* __restrict__ Wq,
                       const float* __restrict__ Wk, const float* __restrict__ Wv,
                       const float* __restrict__ Wfc, const float* __restrict__ hgc_W,
                       __nv_bfloat16* __restrict__ bp) {
    int seg = blockIdx.y;
    int idx = blockIdx.x * 256 + threadIdx.x;
    const float* src; int R, Cc, trans, dstoff;
    if (seg < 4)       { src = gat_W + seg * DD;  R = 128; Cc = 128; trans = 1; dstoff = seg * 16384; }
    else if (seg < 7)  { int j = seg - 4; src = (j == 0 ? Wq : (j == 1 ? Wk : Wv));
                         R = 128; Cc = 256; trans = 1; dstoff = 65536 + j * 32768; }
    else if (seg == 7) { src = Wfc;   R = 256; Cc = 128; trans = 1; dstoff = 163840; }
    else               { src = hgc_W + (seg - 8) * DD; R = 128; Cc = 128; trans = 0;
                         dstoff = 196608 + (seg - 8) * 16384; }
    if (idx >= R * Cc) return;
    int r = idx / Cc, c = idx - r * Cc;
    float v = src[idx];
    int di = trans ? (c * R + r) : idx;
    __nv_bfloat16 h = __float2bfloat16(v);
    bp[dstoff + di] = h;
    bp[BLO_OFF + dstoff + di] = __float2bfloat16(v - __bfloat162float(h));
}

// ---------------------------------------------------------------------------
// mma.sync bf16-split GEMM: C[M, Ntot] = A[M,K](fp32) @ Bt^T (Bt [Ntot,K] bf16 hi/lo)
// BM=128 BN=128 BK=32; 256 threads (2x4 warps, warp tile 64x32)
// grid (ceil(M/128), Ntot/128, nz)
// ---------------------------------------------------------------------------
__global__ __launch_bounds__(256)
void gemm_mma(const float* __restrict__ A0, const float* __restrict__ A1, const float* __restrict__ A2,
              const __nv_bfloat16* __restrict__ B0, const __nv_bfloat16* __restrict__ B1,
              const __nv_bfloat16* __restrict__ B2,
              float* __restrict__ C0, float* __restrict__ C1, float* __restrict__ C2,
              int M, int K, int lda, int ldc) {
    __shared__ __align__(16) uint16_t sA[2][128][40];   // hi/lo, padded stride 40 (80B)
    __shared__ __align__(16) uint16_t sB[2][128][40];
    const float* A = blockIdx.z == 0 ? A0 : (blockIdx.z == 1 ? A1 : A2);
    const __nv_bfloat16* Bh = blockIdx.z == 0 ? B0 : (blockIdx.z == 1 ? B1 : B2);
    const __nv_bfloat16* Bl = Bh + BLO_OFF;
    float* C = blockIdx.z == 0 ? C0 : (blockIdx.z == 1 ? C1 : C2);
    int m0 = blockIdx.x * 128, n0 = blockIdx.y * 128;
    int tid = threadIdx.x, lane = tid & 31, wid = tid >> 5;
    int wm = wid & 1, wn = wid >> 1;      // 2 x 4 warp grid

    float acc[4][4][4];                    // [mf][nf][4]
    #pragma unroll
    for (int i = 0; i < 4; i++)
        #pragma unroll
        for (int j = 0; j < 4; j++) {
            acc[i][j][0] = 0.f; acc[i][j][1] = 0.f; acc[i][j][2] = 0.f; acc[i][j][3] = 0.f;
        }

    // per-lane ldmatrix smem addresses (constant across k-chunks)
    // A (non-trans): matrices = {m0-7,k0-7},{m8-15,k0-7},{m0-7,k8-15},{m8-15,k8-15}
    uint32_t aArow = smem_u32(&sA[0][wm * 64 + (lane & 15)][(lane >> 4) * 8]);
    uint32_t aAlo  = aArow + 128 * 40 * 2;
    // B (non-trans on [n][k]): matrix j = same 8 n-rows, k-block j*8
    uint32_t aBrow = smem_u32(&sB[0][wn * 32 + (lane & 7)][((lane >> 3) & 3) * 8]);
    uint32_t aBlo  = aBrow + 128 * 40 * 2;

    for (int kc = 0; kc < K; kc += 32) {
        // --- A tile: 128x32 fp32 -> bf16 hi/lo ---
        #pragma unroll
        for (int i = 0; i < 4; i++) {
            int idx = i * 256 + tid;
            int r = idx >> 3, c4 = (idx & 7) << 2;
            float4 v = make_float4(0.f, 0.f, 0.f, 0.f);
            int gr = m0 + r;
            if (gr < M) v = *(const float4*)(A + (size_t)gr * lda + kc + c4);
            __nv_bfloat16 h0 = __float2bfloat16(v.x), h1 = __float2bfloat16(v.y);
            __nv_bfloat16 h2 = __float2bfloat16(v.z), h3 = __float2bfloat16(v.w);
            *(uint2*)&sA[0][r][c4] = make_uint2(pack_bf2(h0, h1), pack_bf2(h2, h3));
            __nv_bfloat16 l0 = __float2bfloat16(v.x - __bfloat162float(h0));
            __nv_bfloat16 l1 = __float2bfloat16(v.y - __bfloat162float(h1));
            __nv_bfloat16 l2 = __float2bfloat16(v.z - __bfloat162float(h2));
            __nv_bfloat16 l3 = __float2bfloat16(v.w - __bfloat162float(h3));
            *(uint2*)&sA[1][r][c4] = make_uint2(pack_bf2(l0, l1), pack_bf2(l2, l3));
        }
        // --- B tile: 128x32 bf16 hi/lo copy ---
        #pragma unroll
        for (int i = 0; i < 4; i++) {
            int idx = i * 256 + tid;
            int r = idx >> 3, c4 = (idx & 7) << 2;
            size_t so = (size_t)(n0 + r) * K + kc + c4;
            *(uint2*)&sB[0][r][c4] = *(const uint2*)(Bh + so);
            *(uint2*)&sB[1][r][c4] = *(const uint2*)(Bl + so);
        }
        __syncthreads();

        // B fragments: x4 NON-trans per nf; reg j = k-block j*8 (j=2*ks+b)
        uint32_t bh[4][4], bl[4][4];
        #pragma unroll
        for (int nf = 0; nf < 4; nf++) {
            LDMX4(bh[nf], aBrow + nf * 8 * 80);
            LDMX4(bl[nf], aBlo  + nf * 8 * 80);
        }
        #pragma unroll
        for (int ks = 0; ks < 2; ks++) {
            uint32_t ah[4][4], al[4][4];
            #pragma unroll
            for (int mf = 0; mf < 4; mf++) {
                LDMX4(ah[mf], aArow + mf * 16 * 80 + ks * 32);
                LDMX4(al[mf], aAlo  + mf * 16 * 80 + ks * 32);
            }
            #pragma unroll
            for (int mf = 0; mf < 4; mf++)
                #pragma unroll
                for (int nf = 0; nf < 4; nf++) {
                    MMA16816(acc[mf][nf], ah[mf], bh[nf][2 * ks], bh[nf][2 * ks + 1]);
                    MMA16816(acc[mf][nf], ah[mf], bl[nf][2 * ks], bl[nf][2 * ks + 1]);
                    MMA16816(acc[mf][nf], al[mf], bh[nf][2 * ks], bh[nf][2 * ks + 1]);
                }
        }
        __syncthreads();
    }

    // --- epilogue: scatter accum to C ---
    int rbase = m0 + wm * 64 + (lane >> 2);
    int cbase = n0 + wn * 32 + (lane & 3) * 2;
    #pragma unroll
    for (int mf = 0; mf < 4; mf++) {
        int r0 = rbase + mf * 16;
        #pragma unroll
        for (int nf = 0; nf < 4; nf++) {
            int c = cbase + nf * 8;
            if (r0 < M)
                *(float2*)(C + (size_t)r0 * ldc + c) = make_float2(acc[mf][nf][0], acc[mf][nf][1]);
            if (r0 + 8 < M)
                *(float2*)(C + (size_t)(r0 + 8) * ldc + c) = make_float2(acc[mf][nf][2], acc[mf][nf][3]);
        }
    }
}

// ---------------------------------------------------------------------------
// ELL adjacency build
// ---------------------------------------------------------------------------
__global__ void ell_build(const float* __restrict__ adj0, const float* __restrict__ adj1,
                          int* __restrict__ cols, float* __restrict__ vals,
                          int* __restrict__ cnt) {
    int br = blockIdx.y, n = blockIdx.x, tid = threadIdx.x;
    const float* row = (br ? adj1 : adj0) + (size_t)n * kN;
    __shared__ int sh[128];
    int c = 0;
    for (int m = tid; m < kN; m += 128) if (row[m] > 0.f) c++;
    sh[tid] = c;
    __syncthreads();
    int off = 0;
    for (int i = 0; i < tid; i++) off += sh[i];
    size_t base = (size_t)(br * kN + n) * 128;
    int pos = off;
    for (int m = tid; m < kN; m += 128) {
        float v = row[m];
        if (v > 0.f) {
            if (pos < 128) { cols[base + pos] = m; vals[base + pos] = v; }
            pos++;
        }
    }
    if (tid == 127) cnt[br * kN + n] = min(off + c, 128);
}

// ---------------------------------------------------------------------------
// Relation aggregator
// ---------------------------------------------------------------------------
__global__ void rel_agg_kernel(const float* __restrict__ ra0, const float* __restrict__ ra1,
                               const float* __restrict__ rel0, const float* __restrict__ rel1,
                               float* __restrict__ outp) {
    int br = blockIdx.y, n = blockIdx.x, d = threadIdx.x;
    const float* row = (br ? ra1 : ra0) + (size_t)n * kR;
    const float* rel = br ? rel1 : rel0;
    __shared__ float sh[128];
    float acc = 0.f, rs = 0.f;
    for (int r0 = 0; r0 < kR; r0 += 128) {
        int r = r0 + d;
        sh[d] = (r < kR) ? row[r] : 0.f;
        __syncthreads();
        int lim = min(128, kR - r0);
        for (int j = 0; j < lim; j++) {
            float v = sh[j];
            if (v != 0.f) { rs += v; acc += v * rel[(size_t)(r0 + j) * 128 + d]; }
        }
        __syncthreads();
    }
    outp[((size_t)br * kN + n) * 128 + d] = acc / rs;
}

// ---------------------------------------------------------------------------
// GAT attention scores; Hc layout [br][n][256]
// ---------------------------------------------------------------------------
__global__ void compute_esed(const float* __restrict__ Hc, const float* __restrict__ asrc,
                             const float* __restrict__ adst,
                             float* __restrict__ es, float* __restrict__ ed) {
    int br = blockIdx.y, n = blockIdx.x, d = threadIdx.x;
    const float* hrow = Hc + ((size_t)br * kN + n) * 256;
    float h0 = hrow[d], h1 = hrow[128 + d];
    float v;
    v = brsum128(h0 * asrc[d]);        if (d == 0) es[(br * 2 + 0) * kN + n] = v;
    v = brsum128(h1 * asrc[128 + d]);  if (d == 0) es[(br * 2 + 1) * kN + n] = v;
    v = brsum128(h0 * adst[d]);        if (d == 0) ed[(br * 2 + 0) * kN + n] = v;
    v = brsum128(h1 * adst[128 + d]);  if (d == 0) ed[(br * 2 + 1) * kN + n] = v;
}

// ---------------------------------------------------------------------------
// GAT aggregation + head mean + elu + normalize; writes into seq slot
// ---------------------------------------------------------------------------
__global__ void gat_attn(const float* __restrict__ Hc, const float* __restrict__ es,
                         const float* __restrict__ ed, const int* __restrict__ cols,
                         const int* __restrict__ cnt, float* __restrict__ seq, int slot) {
    int br = blockIdx.y, n = blockIdx.x, tid = threadIdx.x;
    int rb = br * kN + n;
    int c = cnt[rb];
    size_t base = (size_t)rb * 128;
    __shared__ int csh[128];
    __shared__ float wsh[2][128];
    if (tid < c) csh[tid] = cols[base + tid];
    __syncthreads();
    #pragma unroll
    for (int h = 0; h < 2; h++) {
        float esn = es[(br * 2 + h) * kN + n];
        const float* edh = ed + (size_t)(br * 2 + h) * kN;
        float z = -1e30f;
        if (tid < c) {
            z = esn + edh[csh[tid]];
            z = z > 0.f ? z : 0.2f * z;
        }
        float mx = brmax128(z);
        float ex = (tid < c) ? expf(z - mx) : 0.f;
        float se = brsum128(ex);
        if (tid < c) wsh[h][tid] = ex / se;
    }
    __syncthreads();
    const float* Hb = Hc + (size_t)br * kN * 256;
    float a0 = 0.f, a1 = 0.f;
    for (int j = 0; j < c; j++) {
        size_t ro = (size_t)csh[j] * 256 + tid;
        a0 += wsh[0][j] * Hb[ro];
        a1 += wsh[1][j] * Hb[ro + 128];
    }
    float acc = 0.5f * (a0 + a1);
    acc = acc > 0.f ? acc : expm1f(acc);
    float nrm = sqrtf(brsum128(acc * acc));
    seq[(size_t)rb * 384 + slot * 128 + tid] = acc / fmaxf(nrm, 1e-12f);
}

// ---------------------------------------------------------------------------
// Per-node MHA (L=3, H=2, D=128)
// ---------------------------------------------------------------------------
__global__ void mha_attn(const float* __restrict__ Q, const float* __restrict__ Kb,
                         const float* __restrict__ V, float* __restrict__ OC) {
    int n = blockIdx.x, tid = threadIdx.x;
    __shared__ float q[3][256], k[3][256], v[3][256];
    __shared__ float att[2][3][3];
    size_t base = (size_t)n * 3 * 256;
    for (int idx = tid; idx < 768; idx += 128) {
        int l = idx >> 8, j = idx & 255;
        q[l][j] = Q[base + (size_t)l * 256 + j];
        k[l][j] = Kb[base + (size_t)l * 256 + j];
        v[l][j] = V[base + (size_t)l * 256 + j];
    }
    __syncthreads();
    int wid = tid >> 5, lane = tid & 31;
    const float scale = 0.08838834764831845f;
    for (int t = wid; t < 18; t += 4) {
        int h = t / 9, l = (t % 9) / 3, m = t % 3;
        float s = 0.f;
        for (int d = lane; d < 128; d += 32) s += q[l][h * 128 + d] * k[m][h * 128 + d];
        #pragma unroll
        for (int o = 16; o > 0; o >>= 1) s += __shfl_down_sync(0xffffffffu, s, o);
        if (lane == 0) att[h][l][m] = s * scale;
    }
    __syncthreads();
    if (tid < 6) {
        int h = tid / 3, l = tid % 3;
        float m0 = att[h][l][0], m1 = att[h][l][1], m2 = att[h][l][2];
        float mx = fmaxf(m0, fmaxf(m1, m2));
        float e0 = expf(m0 - mx), e1 = expf(m1 - mx), e2 = expf(m2 - mx);
        float ss = e0 + e1 + e2;
        att[h][l][0] = e0 / ss; att[h][l][1] = e1 / ss; att[h][l][2] = e2 / ss;
    }
    __syncthreads();
    int d = tid;
    #pragma unroll
    for (int h = 0; h < 2; h++) {
        #pragma unroll
        for (int l = 0; l < 3; l++) {
            float o = att[h][l][0] * v[0][h * 128 + d]
                    + att[h][l][1] * v[1][h * 128 + d]
                    + att[h][l][2] * v[2][h * 128 + d];
            OC[base + (size_t)l * 256 + h * 128 + d] = o;
        }
    }
}

// ---------------------------------------------------------------------------
// MHA epilogue: residual + LN + mean over L
// ---------------------------------------------------------------------------
__global__ void mha_epilogue(const float* __restrict__ FCO, const float* __restrict__ seq,
                             const float* __restrict__ g, const float* __restrict__ b,
                             const float* __restrict__ relagg, float* __restrict__ out) {
    int br = blockIdx.y, n = blockIdx.x, d = threadIdx.x;
    size_t rb = (size_t)br * kN + n;
    float accmean = 0.f;
    for (int l = 0; l < 3; l++) {
        size_t idx = rb * 384 + l * 128 + d;
        float o = FCO[idx] + seq[idx];
        float mu = brsum128(o) * (1.f / 128.f);
        float c = o - mu;
        float var = brsum128(c * c) * (1.f / 128.f);
        accmean += g[d] * c * rsqrtf(var + 1e-6f) + b[d];
    }
    float* ob = out + (size_t)br * kN * 256;
    ob[(size_t)n * 256 + d] = accmean * (1.f / 3.f);
    ob[(size_t)n * 256 + 128 + d] = relagg[rb * 128 + d];
}

// ---------------------------------------------------------------------------
// Hyperbolic ops
// ---------------------------------------------------------------------------
__global__ void k_init(const float* __restrict__ e0, const float* __restrict__ e1,
                       float* __restrict__ t1, float* __restrict__ seq) {
    int br = blockIdx.y, n = blockIdx.x, d = threadIdx.x;
    const float* in = br ? e1 : e0;
    float u = in[(size_t)n * 128 + d];
    size_t rb = (size_t)br * kN + n;
    seq[rb * 384 + d] = u;
    float nn = fmaxf(sqrtf(brsum128(u * u)), 1e-15f);
    float p = tanhf(nn) * u / nn;
    float pn = fmaxf(sqrtf(brsum128(p * p)), 1e-15f);
    if (pn > MAXN) p *= MAXN / pn;
    float pn2 = fmaxf(sqrtf(brsum128(p * p)), 1e-15f);
    t1[rb * 128 + d] = atanhf(fminf(pn2, 1.f - 1e-7f)) * p / pn2;
}

__global__ void k_bias(const float* __restrict__ b, float* __restrict__ bb) {
    int i = blockIdx.x, d = threadIdx.x;
    float u = b[i * 128 + d];
    float nn = fmaxf(sqrtf(brsum128(u * u)), 1e-15f);
    float p = tanhf(nn) * u / nn;
    float pn = fmaxf(sqrtf(brsum128(p * p)), 1e-15f);
    if (pn > MAXN) p *= MAXN / pn;
    float y2 = brsum128(p * p);
    bb[i * 132 + d] = p;
    if (d == 0) bb[i * 132 + 128] = y2;
}

__global__ void k_hyplinear(const float* __restrict__ U, const float* __restrict__ bb,
                            float* __restrict__ outp) {
    int n = blockIdx.x, d = threadIdx.x;
    float u = U[(size_t)n * 128 + d];
    float nn = fmaxf(sqrtf(brsum128(u * u)), 1e-15f);
    float x = tanhf(nn) * u / nn;
    float xn = fmaxf(sqrtf(brsum128(x * x)), 1e-15f);
    if (xn > MAXN) x *= MAXN / xn;
    float y = bb[d];
    float y2 = bb[128];
    float x2 = brsum128(x * x);
    float xy = brsum128(x * y);
    float num = (1.f + 2.f * xy + y2) * x + (1.f - x2) * y;
    float den = fmaxf(1.f + 2.f * xy + x2 * y2, 1e-15f);
    float h = num / den;
    float hn = fmaxf(sqrtf(brsum128(h * h)), 1e-15f);
    if (hn > MAXN) h *= MAXN / hn;
    float hn2 = fmaxf(sqrtf(brsum128(h * h)), 1e-15f);
    outp[(size_t)n * 128 + d] = atanhf(fminf(hn2, 1.f - 1e-7f)) * h / hn2;
}

__global__ void spmm_hypact(const int* __restrict__ cols, const float* __restrict__ vals,
                            const int* __restrict__ cnt, const float* __restrict__ X,
                            float* __restrict__ t1) {
    int br = blockIdx.y, n = blockIdx.x, tid = threadIdx.x;
    int rb = br * kN + n;
    int c = cnt[rb];
    size_t base = (size_t)rb * 128;
    __shared__ int csh[128];
    __shared__ float vsh[128];
    if (tid < c) { csh[tid] = cols[base + tid]; vsh[tid] = vals[base + tid]; }
    __syncthreads();
    const float* Xb = X + (size_t)br * kN * 128;
    float u = 0.f;
    for (int j = 0; j < c; j++)
        u += vsh[j] * Xb[(size_t)csh[j] * 128 + tid];
    float nn = fmaxf(sqrtf(brsum128(u * u)), 1e-15f);
    float x = tanhf(nn) * u / nn;
    float xn = fmaxf(sqrtf(brsum128(x * x)), 1e-15f);
    if (xn > MAXN) x *= MAXN / xn;
    float n2 = fmaxf(sqrtf(brsum128(x * x)), 1e-15f);
    float l = atanhf(fminf(n2, 1.f - 1e-7f)) * x / n2;
    float r = fmaxf(l, 0.f);
    float n3 = fmaxf(sqrtf(brsum128(r * r)), 1e-15f);
    float y = tanhf(n3) * r / n3;
    float yn = fmaxf(sqrtf(brsum128(y * y)), 1e-15f);
    if (yn > MAXN) y *= MAXN / yn;
    float yn2 = fmaxf(sqrtf(brsum128(y * y)), 1e-15f);
    t1[base + tid] = atanhf(fminf(yn2, 1.f - 1e-7f)) * y / yn2;
}

__global__ void k_finish(const float* __restrict__ t1, const float* __restrict__ e0,
                         const float* __restrict__ e1, const float* __restrict__ relagg,
                         float* __restrict__ out) {
    int br = blockIdx.y, n = blockIdx.x, d = threadIdx.x;
    size_t rb = (size_t)br * kN + n;
    const float* ent = br ? e1 : e0;
    float* ob = out + (size_t)(2 + br) * kN * 256;
    ob[(size_t)n * 256 + d] = ent[(size_t)n * 128 + d] + t1[rb * 128 + d];
    ob[(size_t)n * 256 + 128 + d] = relagg[rb * 128 + d];
}

// ---------------------------------------------------------------------------
// Host side
// ---------------------------------------------------------------------------
extern "C" void kernel_launch(void* const* d_in, const int* in_sizes, int n_in,
                              void* d_out, int out_size) {
    (void)in_sizes; (void)n_in; (void)out_size;
    const float* ent_sr     = (const float*)d_in[0];
    const float* ent_tg     = (const float*)d_in[1];
    const float* rel_sr     = (const float*)d_in[2];
    const float* rel_tg     = (const float*)d_in[3];
    const float* adj_sr     = (const float*)d_in[4];
    const float* adj_tg     = (const float*)d_in[5];
    const float* rel_adj_sr = (const float*)d_in[6];
    const float* rel_adj_tg = (const float*)d_in[7];
    const float* gat_W      = (const float*)d_in[8];
    const float* gat_a_src  = (const float*)d_in[9];
    const float* gat_a_dst  = (const float*)d_in[10];
    const float* Wq         = (const float*)d_in[11];
    const float* Wk         = (const float*)d_in[12];
    const float* Wv         = (const float*)d_in[13];
    const float* Wfc        = (const float*)d_in[14];
    const float* ln_g       = (const float*)d_in[15];
    const float* ln_b       = (const float*)d_in[16];
    const float* hgc_W      = (const float*)d_in[17];
    const float* hgc_b      = (const float*)d_in[18];
    float* out = (float*)d_out;

    float* FP; int* IP; __nv_bfloat16* BP;
    cudaGetSymbolAddress((void**)&FP, g_fpool);
    cudaGetSymbolAddress((void**)&IP, g_ipool);
    cudaGetSymbolAddress((void**)&BP, g_bpool);

    float* relagg = FP + OF_RELAGG;
    float* Hc   = FP + OF_HC;
    float* t3   = FP + OF_T3;
    float* es   = FP + OF_ES;
    float* ed   = FP + OF_ED;
    float* seq  = FP + OF_SEQ;
    float* qb   = FP + OF_QB;
    float* kb   = FP + OF_KB;
    float* vb   = FP + OF_VB;
    float* oc   = FP + OF_OC;
    float* fco  = FP + OF_FCO;
    float* t1   = FP + OF_T1;
    float* t2   = FP + OF_T2;
    float* bb   = FP + OF_BB;
    float* vals = FP + OF_VALS;
    int* cols = IP + IO_COLS;
    int* cnt  = IP + IO_CNT;

    dim3 gN2(kN, 2);

    conv_w<<<dim3(128, 10), 256>>>(gat_W, Wq, Wk, Wv, Wfc, hgc_W, BP);
    ell_build<<<gN2, 128>>>(adj_sr, adj_tg, cols, vals, cnt);
    rel_agg_kernel<<<gN2, 128>>>(rel_adj_sr, rel_adj_tg, rel_sr, rel_tg, relagg);
    k_bias<<<2, 128>>>(hgc_b, bb);
    k_init<<<gN2, 128>>>(ent_sr, ent_tg, t1, seq);

    float* Hc0 = Hc;
    float* Hc1 = Hc + (size_t)kN * 256;
    float* seq1 = seq + (size_t)kN * 384;

    __nv_bfloat16* Wg0 = BP;                 // layer0 combined [256,128]
    __nv_bfloat16* Wg1 = BP + 32768;         // layer1
    __nv_bfloat16* Bq  = BP + 65536;
    __nv_bfloat16* Bk  = BP + 65536 + 32768;
    __nv_bfloat16* Bv  = BP + 65536 + 65536;
    __nv_bfloat16* Bf  = BP + 163840;        // [128,256]
    __nv_bfloat16* Wh0 = BP + 196608;
    __nv_bfloat16* Wh1 = BP + 196608 + 16384;

    // ---- GAT layer 0 (Ntot=256 covers both heads) ----
    gemm_mma<<<dim3(47, 2, 2), 256>>>(ent_sr, ent_tg, ent_tg,
                                      Wg0, Wg0, Wg0, Hc0, Hc1, Hc1,
                                      kN, 128, 128, 256);
    compute_esed<<<gN2, 128>>>(Hc, gat_a_src, gat_a_dst, es, ed);
    gat_attn<<<gN2, 128>>>(Hc, es, ed, cols, cnt, seq, 1);

    // ---- GAT layer 1 (A = seq slot 1, lda=384) ----
    gemm_mma<<<dim3(47, 2, 2), 256>>>(seq + 128, seq1 + 128, seq1 + 128,
                                      Wg1, Wg1, Wg1, Hc0, Hc1, Hc1,
                                      kN, 128, 384, 256);
    compute_esed<<<gN2, 128>>>(Hc, gat_a_src + 256, gat_a_dst + 256, es, ed);
    gat_attn<<<gN2, 128>>>(Hc, es, ed, cols, cnt, seq, 2);

    // ---- MHA over [x0,h1,h2] ----
    gemm_mma<<<dim3(282, 2, 3), 256>>>(seq, seq, seq, Bq, Bk, Bv, qb, kb, vb,
                                       36000, 128, 128, 256);
    mha_attn<<<12000, 128>>>(qb, kb, vb, oc);
    gemm_mma<<<dim3(282, 1, 1), 256>>>(oc, oc, oc, Bf, Bf, Bf, fco, fco, fco,
                                       36000, 256, 256, 128);
    mha_epilogue<<<gN2, 128>>>(fco, seq, ln_g, ln_b, relagg, out);

    // ---- Hyperbolic encoder ----
    for (int i = 0; i < 2; i++) {
        __nv_bfloat16* Whi = i ? Wh1 : Wh0;
        gemm_mma<<<dim3(94, 1, 1), 256>>>(t1, t1, t1, Whi, Whi, Whi, t2, t2, t2,
                                          12000, 128, 128, 128);
        k_hyplinear<<<12000, 128>>>(t2, bb + i * 132, t3);
        spmm_hypact<<<gN2, 128>>>(cols, vals, cnt, t3, t1);
    }
    k_finish<<<gN2, 128>>>(t1, ent_sr, ent_tg, relagg, out);
}